// round 5
// baseline (speedup 1.0000x reference)
#include <cuda_runtime.h>
#include <math.h>

#define BATCH    64
#define IN_SIZE  1024
#define IN_DIM   256
#define HEADS    4
#define OUT_SIZE 64
#define OUT_DIM  256
#define NMAT     (BATCH * HEADS)     /* 256 */
#define HID      (HEADS * IN_DIM)    /* 1024 */
#define MAX_ITER 10

// ---------------------------------------------------------------------------
// Scratch (no dynamic allocation allowed)
// ---------------------------------------------------------------------------
__device__ float g_K[(size_t)NMAT * IN_SIZE * OUT_SIZE];   // 64 MB: exp(x·Wᵀ/eps), [n][s][o]
__device__ float g_u[(size_t)NMAT * IN_SIZE];              // final sinkhorn u
__device__ float g_v[(size_t)NMAT * OUT_SIZE];             // final sinkhorn v
__device__ float g_att[(size_t)BATCH * OUT_SIZE * HID];    // 16 MB: pre-linear activations

// ---------------------------------------------------------------------------
// Kernel 1: K[n][s][o] = exp( (x[b,s,:]·W[h,o,:]) * 10 ),  n = b*4+h
// Tiled SGEMM: BM=128(s) x BN=64(o) x BK=32(d), 256 threads, 8x4 per thread.
// ---------------------------------------------------------------------------
__global__ __launch_bounds__(256) void gemm_k_kernel(const float* __restrict__ x,
                                                     const float* __restrict__ W) {
    const int BM = 128, BK = 32;
    __shared__ float As[BK][BM + 1];      // [k][m]
    __shared__ float Bs[BK][OUT_SIZE + 1];// [k][o]

    int n_id = blockIdx.y;
    int b = n_id >> 2, h = n_id & 3;
    int s0 = blockIdx.x * BM;
    const float* xg = x + ((size_t)b * IN_SIZE + s0) * IN_DIM;
    const float* wg = W + (size_t)h * OUT_SIZE * IN_DIM;

    int tid  = threadIdx.x;
    int trow = tid >> 4;        // 0..15 -> m = trow*8 + i
    int tcol = tid & 15;        // 0..15 -> o = tcol + 16*j
    int lrow = tid >> 3;        // 0..31
    int lcol = (tid & 7) * 4;   // 0..28

    float acc[8][4];
    #pragma unroll
    for (int i = 0; i < 8; ++i)
        #pragma unroll
        for (int j = 0; j < 4; ++j) acc[i][j] = 0.f;

    for (int k0 = 0; k0 < IN_DIM; k0 += BK) {
        #pragma unroll
        for (int p = 0; p < 4; ++p) {
            float4 v = *(const float4*)(xg + (size_t)(lrow + p * 32) * IN_DIM + k0 + lcol);
            As[lcol + 0][lrow + p * 32] = v.x;
            As[lcol + 1][lrow + p * 32] = v.y;
            As[lcol + 2][lrow + p * 32] = v.z;
            As[lcol + 3][lrow + p * 32] = v.w;
        }
        #pragma unroll
        for (int p = 0; p < 2; ++p) {
            float4 v = *(const float4*)(wg + (size_t)(lrow + p * 32) * IN_DIM + k0 + lcol);
            Bs[lcol + 0][lrow + p * 32] = v.x;
            Bs[lcol + 1][lrow + p * 32] = v.y;
            Bs[lcol + 2][lrow + p * 32] = v.z;
            Bs[lcol + 3][lrow + p * 32] = v.w;
        }
        __syncthreads();
        #pragma unroll
        for (int k = 0; k < BK; ++k) {
            float a[8], bb[4];
            #pragma unroll
            for (int i = 0; i < 8; ++i) a[i] = As[k][trow * 8 + i];
            #pragma unroll
            for (int j = 0; j < 4; ++j) bb[j] = Bs[k][tcol + 16 * j];
            #pragma unroll
            for (int i = 0; i < 8; ++i)
                #pragma unroll
                for (int j = 0; j < 4; ++j) acc[i][j] = fmaf(a[i], bb[j], acc[i][j]);
        }
        __syncthreads();
    }

    float* kg = g_K + ((size_t)n_id * IN_SIZE + s0) * OUT_SIZE;
    #pragma unroll
    for (int i = 0; i < 8; ++i) {
        int s = trow * 8 + i;
        #pragma unroll
        for (int j = 0; j < 4; ++j)
            kg[(size_t)s * OUT_SIZE + tcol + 16 * j] = expf(acc[i][j] * 10.0f);
    }
}

// ---------------------------------------------------------------------------
// Kernel 2: Sinkhorn, one CTA per n (256 CTAs, 1024 threads = 32 warps).
// Fused iteration: one pass over K per iteration computes u then accumulates
// the new-v partials from the same K registers. u/v written out at the end.
// Mask is read as int32 (bool input widened by the harness; a nonzero test is
// also correct if it was widened to float32, since 1.0f != 0 bitwise).
// ---------------------------------------------------------------------------
__global__ __launch_bounds__(1024) void sinkhorn_kernel(const int* __restrict__ mask) {
    int n = blockIdx.x;
    int b = n >> 2;
    __shared__ float sm_mask[IN_SIZE];
    __shared__ float sm_u[IN_SIZE];
    __shared__ float sm_v[OUT_SIZE];
    __shared__ float sm_vacc[32][OUT_SIZE];
    __shared__ float sm_red[32];
    __shared__ float sm_a;

    int tid = threadIdx.x, lane = tid & 31, wid = tid >> 5;

    float m = (mask[(size_t)b * IN_SIZE + tid] != 0) ? 1.0f : 0.0f;
    sm_mask[tid] = m;
    float s = m;
    #pragma unroll
    for (int off = 16; off; off >>= 1) s += __shfl_xor_sync(0xffffffffu, s, off);
    if (lane == 0) sm_red[wid] = s;
    if (tid < OUT_SIZE) sm_v[tid] = 1.0f;
    __syncthreads();
    if (tid == 0) {
        float t = 0.f;
        #pragma unroll
        for (int w = 0; w < 32; ++w) t += sm_red[w];
        sm_a = (float)OUT_SIZE / t;
    }
    __syncthreads();
    float a = sm_a;

    const float* Kn = g_K + (size_t)n * IN_SIZE * OUT_SIZE;
    int o0 = lane * 2;     // each lane owns 2 o-columns
    int r0 = wid * 32;     // each warp owns 32 rows

    for (int it = 0; it < MAX_ITER; ++it) {
        float v0 = sm_v[o0], v1 = sm_v[o0 + 1];
        float va0 = 0.f, va1 = 0.f;
        #pragma unroll
        for (int rr = 0; rr < 32; rr += 4) {
            int r = r0 + rr;
            const float* base = Kn + (size_t)r * OUT_SIZE + o0;
            float2 k0 = *(const float2*)(base);
            float2 k1 = *(const float2*)(base + OUT_SIZE);
            float2 k2 = *(const float2*)(base + 2 * OUT_SIZE);
            float2 k3 = *(const float2*)(base + 3 * OUT_SIZE);
            float p0 = fmaf(k0.y, v1, k0.x * v0);
            float p1 = fmaf(k1.y, v1, k1.x * v0);
            float p2 = fmaf(k2.y, v1, k2.x * v0);
            float p3 = fmaf(k3.y, v1, k3.x * v0);
            #pragma unroll
            for (int off = 16; off; off >>= 1) {
                p0 += __shfl_xor_sync(0xffffffffu, p0, off);
                p1 += __shfl_xor_sync(0xffffffffu, p1, off);
                p2 += __shfl_xor_sync(0xffffffffu, p2, off);
                p3 += __shfl_xor_sync(0xffffffffu, p3, off);
            }
            float u0 = sm_mask[r + 0] * (a / p0);
            float u1 = sm_mask[r + 1] * (a / p1);
            float u2 = sm_mask[r + 2] * (a / p2);
            float u3 = sm_mask[r + 3] * (a / p3);
            if (lane == 0) {
                sm_u[r + 0] = u0; sm_u[r + 1] = u1;
                sm_u[r + 2] = u2; sm_u[r + 3] = u3;
            }
            va0 = fmaf(u0, k0.x, va0); va1 = fmaf(u0, k0.y, va1);
            va0 = fmaf(u1, k1.x, va0); va1 = fmaf(u1, k1.y, va1);
            va0 = fmaf(u2, k2.x, va0); va1 = fmaf(u2, k2.y, va1);
            va0 = fmaf(u3, k3.x, va0); va1 = fmaf(u3, k3.y, va1);
        }
        sm_vacc[wid][o0]     = va0;
        sm_vacc[wid][o0 + 1] = va1;
        __syncthreads();
        if (tid < OUT_SIZE) {
            float t = 0.f;
            #pragma unroll
            for (int w = 0; w < 32; ++w) t += sm_vacc[w][tid];
            sm_v[tid] = 1.0f / t;
        }
        __syncthreads();
    }

    g_u[(size_t)n * IN_SIZE + tid] = sm_u[tid];
    if (tid < OUT_SIZE) g_v[(size_t)n * OUT_SIZE + tid] = sm_v[tid];
}

// ---------------------------------------------------------------------------
// Kernel 3: att[b,o,h*256+d] = v[n,o] * sum_s (u[n,s]*K[n,s,o]) * x[b,s,d]
// Per CTA: one n, 128 d-cols. BM=64(o) x BN=128(d) x BK=64(s), 256 threads.
// ---------------------------------------------------------------------------
__global__ __launch_bounds__(256) void attn_kernel(const float* __restrict__ x) {
    const int BN = 128, BK = 64;
    __shared__ float Ks[BK][OUT_SIZE];   // [s][o], u-scaled (16 KB)
    __shared__ float Xs[BK][BN];         // [s][d]          (32 KB)

    int n = blockIdx.y;
    int b = n >> 2, h = n & 3;
    int d0 = blockIdx.x * BN;
    int tid = threadIdx.x;
    int trow = tid >> 4;    // o = trow*4 + i
    int tcol = tid & 15;    // d = tcol + 16*j

    const float* Kn = g_K + (size_t)n * IN_SIZE * OUT_SIZE;
    const float* un = g_u + (size_t)n * IN_SIZE;
    const float* xg = x + (size_t)b * IN_SIZE * IN_DIM + d0;

    float acc[4][8];
    #pragma unroll
    for (int i = 0; i < 4; ++i)
        #pragma unroll
        for (int j = 0; j < 8; ++j) acc[i][j] = 0.f;

    for (int s0 = 0; s0 < IN_SIZE; s0 += BK) {
        #pragma unroll
        for (int p = 0; p < 4; ++p) {
            int r = (tid >> 4) + p * 16;
            float uu = un[s0 + r];
            int c = (tid & 15) * 4;
            float4 kv = *(const float4*)(Kn + (size_t)(s0 + r) * OUT_SIZE + c);
            kv.x *= uu; kv.y *= uu; kv.z *= uu; kv.w *= uu;
            *(float4*)&Ks[r][c] = kv;
        }
        #pragma unroll
        for (int p = 0; p < 8; ++p) {
            int r = (tid >> 5) + p * 8;
            int c = (tid & 31) * 4;
            float4 xv = *(const float4*)(xg + (size_t)(s0 + r) * IN_DIM + c);
            *(float4*)&Xs[r][c] = xv;
        }
        __syncthreads();
        #pragma unroll
        for (int k = 0; k < BK; ++k) {
            float av[4], bv[8];
            #pragma unroll
            for (int i = 0; i < 4; ++i) av[i] = Ks[k][trow * 4 + i];
            #pragma unroll
            for (int j = 0; j < 8; ++j) bv[j] = Xs[k][tcol + 16 * j];
            #pragma unroll
            for (int i = 0; i < 4; ++i)
                #pragma unroll
                for (int j = 0; j < 8; ++j) acc[i][j] = fmaf(av[i], bv[j], acc[i][j]);
        }
        __syncthreads();
    }

    const float* vn = g_v + (size_t)n * OUT_SIZE;
    #pragma unroll
    for (int i = 0; i < 4; ++i) {
        int o = trow * 4 + i;
        float vv = vn[o];
        float* og = g_att + (size_t)(b * OUT_SIZE + o) * HID + (size_t)h * IN_DIM + d0;
        #pragma unroll
        for (int j = 0; j < 8; ++j) og[tcol + 16 * j] = vv * acc[i][j];
    }
}

// ---------------------------------------------------------------------------
// Kernel 4: out[m, :] = relu(att[m, :] @ lin_wᵀ + lin_b), m = b*64+o (4096 rows)
// BM=64 x BN=64 x BK=32, 256 threads, 4x4 per thread.
// ---------------------------------------------------------------------------
__global__ __launch_bounds__(256) void linear_kernel(const float* __restrict__ lw,
                                                     const float* __restrict__ lb,
                                                     float* __restrict__ out) {
    const int BM = 64, BN = 64, BK = 32;
    __shared__ float As[BK][BM + 1];
    __shared__ float Bs[BK][BN + 1];

    int m0 = blockIdx.x * BM;
    int n0 = blockIdx.y * BN;
    int tid = threadIdx.x;
    int trow = tid >> 4, tcol = tid & 15;
    int lrow = tid >> 3;
    int lcol = (tid & 7) * 4;

    float acc[4][4];
    #pragma unroll
    for (int i = 0; i < 4; ++i)
        #pragma unroll
        for (int j = 0; j < 4; ++j) acc[i][j] = 0.f;

    for (int k0 = 0; k0 < HID; k0 += BK) {
        #pragma unroll
        for (int p = 0; p < 2; ++p) {
            float4 v = *(const float4*)(g_att + (size_t)(m0 + lrow + p * 32) * HID + k0 + lcol);
            As[lcol + 0][lrow + p * 32] = v.x;
            As[lcol + 1][lrow + p * 32] = v.y;
            As[lcol + 2][lrow + p * 32] = v.z;
            As[lcol + 3][lrow + p * 32] = v.w;
            float4 w = *(const float4*)(lw + (size_t)(n0 + lrow + p * 32) * HID + k0 + lcol);
            Bs[lcol + 0][lrow + p * 32] = w.x;
            Bs[lcol + 1][lrow + p * 32] = w.y;
            Bs[lcol + 2][lrow + p * 32] = w.z;
            Bs[lcol + 3][lrow + p * 32] = w.w;
        }
        __syncthreads();
        #pragma unroll
        for (int k = 0; k < BK; ++k) {
            float a[4], bb[4];
            #pragma unroll
            for (int i = 0; i < 4; ++i) a[i] = As[k][trow * 4 + i];
            #pragma unroll
            for (int j = 0; j < 4; ++j) bb[j] = Bs[k][tcol + 16 * j];
            #pragma unroll
            for (int i = 0; i < 4; ++i)
                #pragma unroll
                for (int j = 0; j < 4; ++j) acc[i][j] = fmaf(a[i], bb[j], acc[i][j]);
        }
        __syncthreads();
    }

    #pragma unroll
    for (int i = 0; i < 4; ++i) {
        int m = m0 + trow * 4 + i;
        #pragma unroll
        for (int j = 0; j < 4; ++j) {
            int nn = n0 + tcol + 16 * j;
            float r = acc[i][j] + lb[nn];
            out[(size_t)m * OUT_DIM + nn] = r > 0.f ? r : 0.f;
        }
    }
}

// ---------------------------------------------------------------------------
// Launch: x, target_mask(bool->int32/f32), W, lin_w, lin_b -> out [64,64,256] f32
// ---------------------------------------------------------------------------
extern "C" void kernel_launch(void* const* d_in, const int* in_sizes, int n_in,
                              void* d_out, int out_size) {
    const float* x    = (const float*)d_in[0];
    const int*   mask = (const int*)d_in[1];
    const float* W    = (const float*)d_in[2];
    const float* lw   = (const float*)d_in[3];
    const float* lb   = (const float*)d_in[4];
    float*       out  = (float*)d_out;

    gemm_k_kernel<<<dim3(IN_SIZE / 128, NMAT), 256>>>(x, W);
    sinkhorn_kernel<<<NMAT, 1024>>>(mask);
    attn_kernel<<<dim3(IN_DIM / 128, NMAT), 256>>>(x);
    linear_kernel<<<dim3(BATCH * OUT_SIZE / 64, OUT_DIM / 64), 256>>>(lw, lb, out);
}